// round 3
// baseline (speedup 1.0000x reference)
#include <cuda_runtime.h>
#include <cuda_bf16.h>
#include <cstdint>

// SparseNonzeroAvgPooling, C = 32.
//   d_in[0]: in_feats  float32 [N_IN * 32]
//   d_in[1]: in_map    int32   [M]        (M = 4,000,000)
//   d_in[2]: out_map   int32   [M]
//   d_in[3]: n_out     int32   [1]        (n_out = 250,000 = out_size/32)
//   d_out  : float32   [n_out * 32]
//
// Strategy: invert the (in,out) pair list into CSR on every call, then do a
// per-output-voxel gather-sum with ZERO float atomics. Removes ~530 MB of L2
// atomic transactions vs. the red.v4 scatter baseline.

#define CCH       32
#define MAXN      262144              // >= n_out, multiple of SCAN_BLK
#define SCAN_BLK  1024
#define MAX_BLKS  (MAXN / SCAN_BLK)   // 256
#define MAXM      4194304             // >= M

__device__ int g_counts[MAXN];
__device__ int g_offsets[MAXN];
__device__ int g_cursor[MAXN];
__device__ int g_blocksums[MAX_BLKS];
__device__ int g_csr[MAXM];           // in_map values grouped by output voxel

// ---------------------------------------------------------------------------
// 1) zero the histogram counters
// ---------------------------------------------------------------------------
__global__ void k_zero_counts(int* __restrict__ counts, int n) {
    int i = blockIdx.x * blockDim.x + threadIdx.x;
    int stride = gridDim.x * blockDim.x;
    for (int j = i; j < n; j += stride) counts[j] = 0;
}

// ---------------------------------------------------------------------------
// 2) histogram of out_map (int atomics, spread over 250K addresses)
// ---------------------------------------------------------------------------
__global__ void k_hist(const int* __restrict__ out_map,
                       int* __restrict__ counts, int M) {
    int p4 = blockIdx.x * blockDim.x + threadIdx.x;
    int base = p4 * 4;
    if (base + 3 < M) {
        int4 o = __ldg((const int4*)(out_map + base));
        atomicAdd(&counts[o.x], 1);
        atomicAdd(&counts[o.y], 1);
        atomicAdd(&counts[o.z], 1);
        atomicAdd(&counts[o.w], 1);
    } else {
        for (int p = base; p < M; p++)
            atomicAdd(&counts[__ldg(&out_map[p])], 1);
    }
}

// ---------------------------------------------------------------------------
// 3) per-block exclusive scan of counts; block totals to g_blocksums
// ---------------------------------------------------------------------------
__global__ void k_scan1(const int* __restrict__ counts,
                        int* __restrict__ offsets,
                        int* __restrict__ blocksums, int n) {
    __shared__ int sh[SCAN_BLK];
    int tid = threadIdx.x;
    int gid = blockIdx.x * SCAN_BLK + tid;
    int v = (gid < n) ? counts[gid] : 0;
    sh[tid] = v;
    __syncthreads();
    for (int off = 1; off < SCAN_BLK; off <<= 1) {
        int t = (tid >= off) ? sh[tid - off] : 0;
        __syncthreads();
        sh[tid] += t;
        __syncthreads();
    }
    int incl = sh[tid];
    if (gid < n) offsets[gid] = incl - v;          // exclusive, partial
    if (tid == SCAN_BLK - 1) blocksums[blockIdx.x] = incl;
}

// ---------------------------------------------------------------------------
// 4) single-block exclusive scan of block sums (<= 256 values)
// ---------------------------------------------------------------------------
__global__ void k_scan2(int* __restrict__ blocksums, int nblocks) {
    __shared__ int sh[MAX_BLKS];
    int tid = threadIdx.x;
    int v = (tid < nblocks) ? blocksums[tid] : 0;
    sh[tid] = v;
    __syncthreads();
    for (int off = 1; off < MAX_BLKS; off <<= 1) {
        int t = (tid >= off) ? sh[tid - off] : 0;
        __syncthreads();
        sh[tid] += t;
        __syncthreads();
    }
    if (tid < nblocks) blocksums[tid] = sh[tid] - v;   // exclusive
}

// ---------------------------------------------------------------------------
// 5) add block prefixes; publish final offsets and a mutable cursor copy
// ---------------------------------------------------------------------------
__global__ void k_scan3(int* __restrict__ offsets,
                        int* __restrict__ cursor,
                        const int* __restrict__ blocksums, int n) {
    int gid = blockIdx.x * blockDim.x + threadIdx.x;
    if (gid >= n) return;
    int o = offsets[gid] + blocksums[gid >> 10];   // SCAN_BLK == 1024
    offsets[gid] = o;
    cursor[gid]  = o;
}

// ---------------------------------------------------------------------------
// 6) fill CSR: place each pair's in_map value into its output segment
// ---------------------------------------------------------------------------
__global__ void k_fill(const int* __restrict__ in_map,
                       const int* __restrict__ out_map,
                       int* __restrict__ cursor,
                       int* __restrict__ csr, int M) {
    int p = blockIdx.x * blockDim.x + threadIdx.x;
    if (p >= M) return;
    int o = __ldg(&out_map[p]);
    int pos = atomicAdd(&cursor[o], 1);
    csr[pos] = __ldg(&in_map[p]);
}

// ---------------------------------------------------------------------------
// 7) gather-sum: one warp per output voxel, lane = channel.
//    Indices staged 32-wide per lane, broadcast via shfl; 4 accumulators
//    keep >=4 independent 128B row loads in flight.
// ---------------------------------------------------------------------------
__global__ void k_gather(const float* __restrict__ feats,
                         const int* __restrict__ offsets,
                         const int* __restrict__ counts,
                         const int* __restrict__ csr,
                         float* __restrict__ out, int n_out) {
    int w = (blockIdx.x * blockDim.x + threadIdx.x) >> 5;
    int lane = threadIdx.x & 31;
    if (w >= n_out) return;

    int s   = __ldg(&offsets[w]);
    int deg = __ldg(&counts[w]);

    float a0 = 0.f, a1 = 0.f, a2 = 0.f, a3 = 0.f;
    for (int base = 0; base < deg; base += 32) {
        int n = min(32, deg - base);
        int idx = (lane < n) ? __ldg(&csr[s + base + lane]) : 0;
        int i = 0;
        for (; i + 4 <= n; i += 4) {
            int r0 = __shfl_sync(0xffffffffu, idx, i);
            int r1 = __shfl_sync(0xffffffffu, idx, i + 1);
            int r2 = __shfl_sync(0xffffffffu, idx, i + 2);
            int r3 = __shfl_sync(0xffffffffu, idx, i + 3);
            a0 += __ldg(&feats[(long long)r0 * CCH + lane]);
            a1 += __ldg(&feats[(long long)r1 * CCH + lane]);
            a2 += __ldg(&feats[(long long)r2 * CCH + lane]);
            a3 += __ldg(&feats[(long long)r3 * CCH + lane]);
        }
        for (; i < n; i++) {
            int r = __shfl_sync(0xffffffffu, idx, i);
            a0 += __ldg(&feats[(long long)r * CCH + lane]);
        }
    }
    float sum = (a0 + a1) + (a2 + a3);
    float scale = 1.0f / fmaxf((float)deg, 1.0f);
    out[(long long)w * CCH + lane] = sum * scale;
}

extern "C" void kernel_launch(void* const* d_in, const int* in_sizes, int n_in,
                              void* d_out, int out_size) {
    const float* feats   = (const float*)d_in[0];
    const int*   in_map  = (const int*)d_in[1];
    const int*   out_map = (const int*)d_in[2];
    float*       out     = (float*)d_out;

    int M     = in_sizes[1];
    int n_out = out_size / CCH;

    int *counts, *offsets, *cursor, *blocksums, *csr;
    cudaGetSymbolAddress((void**)&counts,    g_counts);
    cudaGetSymbolAddress((void**)&offsets,   g_offsets);
    cudaGetSymbolAddress((void**)&cursor,    g_cursor);
    cudaGetSymbolAddress((void**)&blocksums, g_blocksums);
    cudaGetSymbolAddress((void**)&csr,       g_csr);

    int scan_blocks = (n_out + SCAN_BLK - 1) / SCAN_BLK;   // <= 256

    // 1) zero histogram
    k_zero_counts<<<1024, 256>>>(counts, n_out);

    // 2) histogram of out_map
    {
        int quads = (M + 3) / 4;
        k_hist<<<(quads + 255) / 256, 256>>>(out_map, counts, M);
    }

    // 3-5) exclusive scan -> offsets, cursor
    k_scan1<<<scan_blocks, SCAN_BLK>>>(counts, offsets, blocksums, n_out);
    k_scan2<<<1, MAX_BLKS>>>(blocksums, scan_blocks);
    k_scan3<<<(n_out + 255) / 256, 256>>>(offsets, cursor, blocksums, n_out);

    // 6) fill CSR
    k_fill<<<(M + 255) / 256, 256>>>(in_map, out_map, cursor, csr, M);

    // 7) gather-sum + average (writes every output row, incl. zeros)
    {
        long long threads_total = (long long)n_out * 32;
        unsigned blocks = (unsigned)((threads_total + 255) / 256);
        k_gather<<<blocks, 256>>>(feats, offsets, counts, csr, out, n_out);
    }
}